// round 3
// baseline (speedup 1.0000x reference)
#include <cuda_runtime.h>
#include <cstdint>

#define N_NODES 50000
#define A_DIM   65
#define DEG     32
#define HID     16
#define BOT     32
#define WARPS_PER_BLOCK 4

// Weights published to the constant bank once; W2/b2 re-staged to shared per block.
struct WPack {
    float4 L1[HID];          // (Wc0[j], Wc1[j], bc[j], 0)  composed 2->16 layer
    float  b2[BOT];
    float  W2[HID * BOT];    // [16][32] row-major
};
__constant__ WPack cw;
__device__   WPack g_stage;

__global__ void setup_weights_kernel(const float* __restrict__ W_se,
                                     const float* __restrict__ b_se,
                                     const float* __restrict__ W1,
                                     const float* __restrict__ b1,
                                     const float* __restrict__ W2,
                                     const float* __restrict__ b2) {
    int t = threadIdx.x;
    if (t < HID) {
        float wc0 = 0.f, wc1 = 0.f, bc = b1[t];
        #pragma unroll
        for (int e = 0; e < 32; e++) {
            float w1ej = W1[e * HID + t];
            wc0 = fmaf(W_se[e],      w1ej, wc0);
            wc1 = fmaf(W_se[32 + e], w1ej, wc1);
            bc  = fmaf(b_se[e],      w1ej, bc);
        }
        g_stage.L1[t] = make_float4(wc0, wc1, bc, 0.f);
    }
    for (int i = t; i < HID * BOT; i += blockDim.x) g_stage.W2[i] = W2[i];
    if (t < BOT) g_stage.b2[t] = b2[t];
}

__device__ __forceinline__ void fma2(unsigned long long& acc,
                                     unsigned long long a,
                                     unsigned long long b) {
    asm("fma.rn.f32x2 %0, %1, %2, %0;" : "+l"(acc) : "l"(a), "l"(b));
}
__device__ __forceinline__ unsigned long long pack2(float v) {
    unsigned long long r;
    asm("mov.b64 %0, {%1, %1};" : "=l"(r) : "r"(__float_as_uint(v)));
    return r;
}

// Each warp processes TWO nodes; lane d = neighbor d of both nodes.
// W2/b2 live in shared (broadcast LDS.128 = 1 crossbar wavefront),
// composed layer-1 weights in constant (only 16 LDC.128/warp).
__global__ __launch_bounds__(WARPS_PER_BLOCK * 32, 5)
void pooling_net_kernel(const float2* __restrict__ corr,   // [N, 65]
                        const int*    __restrict__ nei,    // [N*32, 3]
                        float*        __restrict__ out) {  // [N, 32]
    __shared__ __align__(16) unsigned long long sW2[HID * 16];  // [j][c_pair]
    __shared__ unsigned long long sb2[16];
    // Transpose-reduce scratch: [warp][neighbor][16 u64] + 1 u64 pad (stride 34 floats)
    __shared__ unsigned long long red[WARPS_PER_BLOCK][DEG][17];

    // Stage W2/b2 from the constant bank into shared (no L2 traffic)
    {
        const unsigned long long* cW2 = (const unsigned long long*)cw.W2;
        for (int i = threadIdx.x; i < HID * 16; i += WARPS_PER_BLOCK * 32)
            sW2[i] = cW2[i];
        if (threadIdx.x < 16)
            sb2[threadIdx.x] = ((const unsigned long long*)cw.b2)[threadIdx.x];
    }
    __syncthreads();

    int warp = (blockIdx.x * blockDim.x + threadIdx.x) >> 5;
    int lane = threadIdx.x & 31;
    int wl   = threadIdx.x >> 5;
    int n0   = warp * 2;
    int n1   = n0 + 1;
    if (n0 >= N_NODES) return;

    // Gather both nodes' neighbor coordinates
    int aA = nei[(n0 * DEG + lane) * 3 + 1];
    int aB = nei[(n1 * DEG + lane) * 3 + 1];
    float2 xA = corr[n0 * A_DIM + aA];
    float2 xB = corr[n1 * A_DIM + aB];

    // Layer 1 (composed 2->16) + relu, both nodes (weights via constant port)
    float h1A[HID], h1B[HID];
    #pragma unroll
    for (int j = 0; j < HID; j++) {
        float4 p = cw.L1[j];
        h1A[j] = fmaxf(fmaf(xA.x, p.x, fmaf(xA.y, p.y, p.z)), 0.f);
        h1B[j] = fmaxf(fmaf(xB.x, p.x, fmaf(xB.y, p.y, p.z)), 0.f);
    }

    // Layer 2 (16->32) packed f32x2; each LDS.128 broadcast feeds 4 FFMA2
    unsigned long long accA[16], accB[16];
    #pragma unroll
    for (int c = 0; c < 16; c++) { accA[c] = sb2[c]; accB[c] = sb2[c]; }

    const ulonglong2* w2v = (const ulonglong2*)sW2;
    #pragma unroll
    for (int j = 0; j < HID; j++) {
        unsigned long long mA = pack2(h1A[j]);
        unsigned long long mB = pack2(h1B[j]);
        #pragma unroll
        for (int cc = 0; cc < 8; cc++) {
            ulonglong2 w = w2v[j * 8 + cc];                 // LDS.128 broadcast
            fma2(accA[2 * cc],     mA, w.x);
            fma2(accA[2 * cc + 1], mA, w.y);
            fma2(accB[2 * cc],     mB, w.x);
            fma2(accB[2 * cc + 1], mB, w.y);
        }
    }

    // Epilogue: transpose via shared, per-channel max; relu folded into pool
    {
        unsigned long long* myrow = &red[wl][lane][0];
        #pragma unroll
        for (int c = 0; c < 16; c++) myrow[c] = accA[c];
        __syncwarp();
        const float* rf = (const float*)&red[wl][0][0];
        float m = 0.f;
        #pragma unroll
        for (int d = 0; d < DEG; d++) m = fmaxf(m, rf[d * 34 + lane]);
        out[n0 * BOT + lane] = m;
        __syncwarp();
    }
    {
        unsigned long long* myrow = &red[wl][lane][0];
        #pragma unroll
        for (int c = 0; c < 16; c++) myrow[c] = accB[c];
        __syncwarp();
        const float* rf = (const float*)&red[wl][0][0];
        float m = 0.f;
        #pragma unroll
        for (int d = 0; d < DEG; d++) m = fmaxf(m, rf[d * 34 + lane]);
        out[n1 * BOT + lane] = m;
    }
}

extern "C" void kernel_launch(void* const* d_in, const int* in_sizes, int n_in,
                              void* d_out, int out_size) {
    const float* corr  = (const float*)d_in[0];   // [N, 65, 2]
    const int*   nei   = (const int*)d_in[1];     // [N*32, 3]
    // d_in[2] = lstm_state (dead)
    const float* W_se  = (const float*)d_in[3];
    const float* b_se  = (const float*)d_in[4];
    const float* W1    = (const float*)d_in[5];
    const float* b1    = (const float*)d_in[6];
    const float* W2    = (const float*)d_in[7];
    const float* b2    = (const float*)d_in[8];
    float* out = (float*)d_out;

    setup_weights_kernel<<<1, 128>>>(W_se, b_se, W1, b1, W2, b2);

    void* stage_ptr = nullptr;
    cudaGetSymbolAddress(&stage_ptr, g_stage);
    cudaMemcpyToSymbolAsync(cw, stage_ptr, sizeof(WPack), 0,
                            cudaMemcpyDeviceToDevice, 0);

    int warps  = (N_NODES + 1) / 2;
    int blocks = (warps + WARPS_PER_BLOCK - 1) / WARPS_PER_BLOCK;
    pooling_net_kernel<<<blocks, WARPS_PER_BLOCK * 32>>>((const float2*)corr, nei, out);
}

// round 4
// speedup vs baseline: 1.6079x; 1.6079x over previous
#include <cuda_runtime.h>
#include <cstdint>

#define N_NODES 50000
#define A_DIM   65
#define DEG     32
#define HID     16
#define BOT     32
#define WARPS_PER_BLOCK 4

typedef unsigned long long u64;

// All weights in the constant bank (lane-invariant -> LDCU uniform path).
struct WPack {
    float4 L1[HID];          // (Wc0[j], Wc1[j], bc[j], 0)  composed 2->16 layer
    float  b2[BOT];
    float  W2[HID * BOT];    // [16][32] row-major
};
__constant__ WPack cw;
__device__   WPack g_stage;

__global__ void setup_weights_kernel(const float* __restrict__ W_se,
                                     const float* __restrict__ b_se,
                                     const float* __restrict__ W1,
                                     const float* __restrict__ b1,
                                     const float* __restrict__ W2,
                                     const float* __restrict__ b2) {
    int t = threadIdx.x;
    if (t < HID) {
        float wc0 = 0.f, wc1 = 0.f, bc = b1[t];
        #pragma unroll
        for (int e = 0; e < 32; e++) {
            float w1ej = W1[e * HID + t];
            wc0 = fmaf(W_se[e],      w1ej, wc0);
            wc1 = fmaf(W_se[32 + e], w1ej, wc1);
            bc  = fmaf(b_se[e],      w1ej, bc);
        }
        g_stage.L1[t] = make_float4(wc0, wc1, bc, 0.f);
    }
    for (int i = t; i < HID * BOT; i += blockDim.x) g_stage.W2[i] = W2[i];
    if (t < BOT) g_stage.b2[t] = b2[t];
}

__device__ __forceinline__ void fma2(u64& acc, u64 a, u64 b) {
    asm("fma.rn.f32x2 %0, %1, %2, %0;" : "+l"(acc) : "l"(a), "l"(b));
}
__device__ __forceinline__ u64 pack2(float v) {
    u64 r;
    asm("mov.b64 %0, {%1, %1};" : "=l"(r) : "r"(__float_as_uint(v)));
    return r;
}

// Per-node epilogue region: 32 neighbor-rows x 9 u64 (8 data + 1 pad) = 288,
// +8 u64 pad between node regions so node1's float base is +16 mod 32 banks
// (node0 reduce-lanes and node1 reduce-lanes hit complementary bank halves).
#define NODE_STRIDE 296

// 2 nodes/warp, lane = neighbor. Layer-2 split into two 16-channel halves to
// halve accumulator registers -> 6 blocks/SM instead of 4.
__global__ __launch_bounds__(WARPS_PER_BLOCK * 32, 6)
void pooling_net_kernel(const float2* __restrict__ corr,   // [N, 65]
                        const int*    __restrict__ nei,    // [N*32, 3]
                        float*        __restrict__ out) {  // [N, 32]
    __shared__ u64 red[WARPS_PER_BLOCK][2 * NODE_STRIDE];

    int warp = (blockIdx.x * blockDim.x + threadIdx.x) >> 5;
    int lane = threadIdx.x & 31;
    int wl   = threadIdx.x >> 5;
    int n0   = warp * 2;
    int n1   = n0 + 1;
    if (n0 >= N_NODES) return;

    // Hoist both gathers to cover LDG latency with layer-1 math
    int aA = nei[(n0 * DEG + lane) * 3 + 1];
    int aB = nei[(n1 * DEG + lane) * 3 + 1];
    float2 xA = corr[n0 * A_DIM + aA];
    float2 xB = corr[n1 * A_DIM + aB];

    // Layer 1 (composed 2->16) + relu, both nodes
    float h1A[HID], h1B[HID];
    #pragma unroll
    for (int j = 0; j < HID; j++) {
        float4 p = cw.L1[j];
        h1A[j] = fmaxf(fmaf(xA.x, p.x, fmaf(xA.y, p.y, p.z)), 0.f);
        h1B[j] = fmaxf(fmaf(xB.x, p.x, fmaf(xB.y, p.y, p.z)), 0.f);
    }

    int node = lane >> 4;          // reduce role: 0 -> node n0, 1 -> node n1
    int ch   = lane & 15;          // reduce role: channel within half
    const float* rbase = (const float*)&red[wl][node * NODE_STRIDE];

    #pragma unroll
    for (int half = 0; half < 2; half++) {
        // Layer 2 half: channels [half*16, half*16+16), 8 packed accs per node
        u64 accA[8], accB[8];
        const u64* b2v = (const u64*)cw.b2 + half * 8;
        #pragma unroll
        for (int c = 0; c < 8; c++) { accA[c] = b2v[c]; accB[c] = b2v[c]; }

        const ulonglong2* w2v = (const ulonglong2*)cw.W2 + half * 4;
        #pragma unroll
        for (int j = 0; j < HID; j++) {
            u64 mA = pack2(h1A[j]);
            u64 mB = pack2(h1B[j]);
            #pragma unroll
            for (int cc = 0; cc < 4; cc++) {
                ulonglong2 w = w2v[j * 8 + cc];        // lane-invariant constant load
                fma2(accA[2 * cc],     mA, w.x);
                fma2(accA[2 * cc + 1], mA, w.y);
                fma2(accB[2 * cc],     mB, w.x);
                fma2(accB[2 * cc + 1], mB, w.y);
            }
        }

        // Transpose both nodes' half through shared; relu folded into max(0, ...)
        u64* rA = &red[wl][0 * NODE_STRIDE + lane * 9];
        u64* rB = &red[wl][1 * NODE_STRIDE + lane * 9];
        #pragma unroll
        for (int c = 0; c < 8; c++) { rA[c] = accA[c]; rB[c] = accB[c]; }
        __syncwarp();

        float m = 0.f;
        #pragma unroll
        for (int d = 0; d < DEG; d++)
            m = fmaxf(m, rbase[d * 18 + ch]);
        out[(n0 + node) * BOT + half * 16 + ch] = m;
        __syncwarp();
    }
}

extern "C" void kernel_launch(void* const* d_in, const int* in_sizes, int n_in,
                              void* d_out, int out_size) {
    const float* corr  = (const float*)d_in[0];   // [N, 65, 2]
    const int*   nei   = (const int*)d_in[1];     // [N*32, 3]
    // d_in[2] = lstm_state (dead)
    const float* W_se  = (const float*)d_in[3];
    const float* b_se  = (const float*)d_in[4];
    const float* W1    = (const float*)d_in[5];
    const float* b1    = (const float*)d_in[6];
    const float* W2    = (const float*)d_in[7];
    const float* b2    = (const float*)d_in[8];
    float* out = (float*)d_out;

    setup_weights_kernel<<<1, 128>>>(W_se, b_se, W1, b1, W2, b2);

    void* stage_ptr = nullptr;
    cudaGetSymbolAddress(&stage_ptr, g_stage);
    cudaMemcpyToSymbolAsync(cw, stage_ptr, sizeof(WPack), 0,
                            cudaMemcpyDeviceToDevice, 0);

    int warps  = (N_NODES + 1) / 2;
    int blocks = (warps + WARPS_PER_BLOCK - 1) / WARPS_PER_BLOCK;
    pooling_net_kernel<<<blocks, WARPS_PER_BLOCK * 32>>>((const float2*)corr, nei, out);
}